// round 2
// baseline (speedup 1.0000x reference)
#include <cuda_runtime.h>
#include <cfloat>
#include <math.h>

#define T_TOK   2048
#define D_DIM   768
#define H_HEADS 4
#define N_KEYS  25600
#define KD      128
#define KNN     16
#define HID_A   44
#define HID_S   1024
#define QDIM    (H_HEADS*KD)   // 512
#define BN_EPS  1e-5f

// ---------------- scratch (device globals; no allocations allowed) ----------
__device__ float g_q[T_TOK * QDIM];
__device__ int   g_topidx[T_TOK * H_HEADS * KNN];
__device__ float g_gates[T_TOK * H_HEADS * KNN];
__device__ float g_comb[T_TOK];
__device__ float g_hid[T_TOK * HID_S];

// ============================================================================
// Kernel 1: q = BN(x @ wq^T + bq)    M=2048, N=512, K=768
// ============================================================================
__global__ void qproj_kernel(const float* __restrict__ x,
                             const float* __restrict__ wq,
                             const float* __restrict__ bq,
                             const float* __restrict__ gamma,
                             const float* __restrict__ beta,
                             const float* __restrict__ mean,
                             const float* __restrict__ var)
{
    __shared__ float sA[16][65];
    __shared__ float sB[16][65];
    const int m0 = blockIdx.x * 64;
    const int n0 = blockIdx.y * 64;
    const int tid = threadIdx.x;
    const int kk = tid & 15, r = tid >> 4;
    const int ty = tid >> 4, tx = tid & 15;

    float acc[4][4] = {};
    for (int k0 = 0; k0 < D_DIM; k0 += 16) {
#pragma unroll
        for (int s = 0; s < 4; ++s) {
            sA[kk][r + 16 * s] = x[(size_t)(m0 + r + 16 * s) * D_DIM + k0 + kk];
            sB[kk][r + 16 * s] = wq[(size_t)(n0 + r + 16 * s) * D_DIM + k0 + kk];
        }
        __syncthreads();
#pragma unroll
        for (int k = 0; k < 16; ++k) {
            float a[4], b[4];
#pragma unroll
            for (int i = 0; i < 4; ++i) { a[i] = sA[k][ty + 16 * i]; b[i] = sB[k][tx + 16 * i]; }
#pragma unroll
            for (int i = 0; i < 4; ++i)
#pragma unroll
                for (int j = 0; j < 4; ++j) acc[i][j] += a[i] * b[j];
        }
        __syncthreads();
    }
#pragma unroll
    for (int i = 0; i < 4; ++i)
#pragma unroll
        for (int j = 0; j < 4; ++j) {
            int m = m0 + ty + 16 * i;
            int n = n0 + tx + 16 * j;
            float v = acc[i][j] + bq[n];
            v = (v - mean[n]) * rsqrtf(var[n] + BN_EPS) * gamma[n] + beta[n];
            g_q[(size_t)m * QDIM + n] = v;
        }
}

// ============================================================================
// Kernel 2: scores = q . keys^T (per head), running top-16 + softmax gates.
// Block: 128 threads, tile = 32 tokens x 128 keys per chunk, 200 chunks.
// Micro-tile 4 tokens x 8 keys per thread, float4 smem loads.
// ============================================================================
#define SKS 132   // padded smem row stride (floats), 16B-aligned, conflict-free

__device__ __forceinline__ void topk_insert(float* tv, int* ti, float v, int idx)
{
    int p = KNN - 1;
    while (p > 0 && tv[p - 1] < v) {
        tv[p] = tv[p - 1];
        ti[p] = ti[p - 1];
        --p;
    }
    tv[p] = v;
    ti[p] = idx;
}

__global__ void scores_topk_kernel(const float* __restrict__ keys)
{
    extern __shared__ float sm[];
    float* sK    = sm;                    // 128*SKS
    float* sQ    = sK + 128 * SKS;        // 32*SKS
    float* sS    = sQ + 32 * SKS;         // 32*SKS
    float* sTopV = sS + 32 * SKS;         // 32*16
    int*   sTopI = (int*)(sTopV + 32 * KNN);

    const int tid = threadIdx.x;          // 128 threads
    const int t0  = blockIdx.x * 32;
    const int h   = blockIdx.y;
    const float* keyh = keys + (size_t)h * N_KEYS * KD;

    // init top lists
    for (int i = tid; i < 32 * KNN; i += 128) sTopV[i] = -FLT_MAX;

    // stage q tile (32 tokens x 128 dims)
    for (int i = tid; i < 32 * 32; i += 128) {
        int row = i >> 5, c4 = i & 31;
        float4 v = *(const float4*)(g_q + (size_t)(t0 + row) * QDIM + h * KD + c4 * 4);
        *(float4*)(sQ + row * SKS + c4 * 4) = v;
    }

    const int tr = tid >> 4;   // 0..7   token group
    const int tc = tid & 15;   // 0..15  key group

    for (int n0 = 0; n0 < N_KEYS; n0 += 128) {
        __syncthreads();   // previous scan finished, sK free
        // stage keys chunk (128 x 128)
        for (int i = tid; i < 128 * 32; i += 128) {
            int row = i >> 5, c4 = i & 31;
            float4 v = *(const float4*)(keyh + (size_t)(n0 + row) * KD + c4 * 4);
            *(float4*)(sK + row * SKS + c4 * 4) = v;
        }
        __syncthreads();

        float acc[4][8];
#pragma unroll
        for (int i = 0; i < 4; ++i)
#pragma unroll
            for (int j = 0; j < 8; ++j) acc[i][j] = 0.f;

#pragma unroll 4
        for (int d = 0; d < KD; d += 4) {
            float4 aa[4], bb[8];
#pragma unroll
            for (int i = 0; i < 4; ++i)
                aa[i] = *(const float4*)(sQ + (tr + 8 * i) * SKS + d);
#pragma unroll
            for (int j = 0; j < 8; ++j)
                bb[j] = *(const float4*)(sK + (tc + 16 * j) * SKS + d);
#pragma unroll
            for (int i = 0; i < 4; ++i)
#pragma unroll
                for (int j = 0; j < 8; ++j) {
                    acc[i][j] = fmaf(aa[i].x, bb[j].x, acc[i][j]);
                    acc[i][j] = fmaf(aa[i].y, bb[j].y, acc[i][j]);
                    acc[i][j] = fmaf(aa[i].z, bb[j].z, acc[i][j]);
                    acc[i][j] = fmaf(aa[i].w, bb[j].w, acc[i][j]);
                }
        }
        // scores to smem
#pragma unroll
        for (int i = 0; i < 4; ++i)
#pragma unroll
            for (int j = 0; j < 8; ++j)
                sS[(tr + 8 * i) * SKS + tc + 16 * j] = acc[i][j];
        __syncthreads();

        // warp 0: each lane maintains top-16 for its token
        if (tid < 32) {
            const float4* row = (const float4*)(sS + tid * SKS);
            float* tv = sTopV + tid * KNN;
            int*   ti = sTopI + tid * KNN;
            float minv = tv[KNN - 1];
            for (int j4 = 0; j4 < 32; ++j4) {
                float4 v = row[j4];
                int base = n0 + 4 * j4;
                if (v.x > minv) { topk_insert(tv, ti, v.x, base + 0); minv = tv[KNN - 1]; }
                if (v.y > minv) { topk_insert(tv, ti, v.y, base + 1); minv = tv[KNN - 1]; }
                if (v.z > minv) { topk_insert(tv, ti, v.z, base + 2); minv = tv[KNN - 1]; }
                if (v.w > minv) { topk_insert(tv, ti, v.w, base + 3); minv = tv[KNN - 1]; }
            }
        }
    }
    __syncthreads();

    // softmax over each token's top-16, write gates + indices
    if (tid < 32) {
        float* tv = sTopV + tid * KNN;
        int*   ti = sTopI + tid * KNN;
        float mx = tv[0];  // sorted desc
        float sum = 0.f;
        float e[KNN];
#pragma unroll
        for (int k = 0; k < KNN; ++k) { e[k] = __expf(tv[k] - mx); sum += e[k]; }
        float inv = 1.f / sum;
        int t = t0 + tid;
        size_t base = ((size_t)t * H_HEADS + h) * KNN;
#pragma unroll
        for (int k = 0; k < KNN; ++k) {
            g_gates[base + k]  = e[k] * inv;
            g_topidx[base + k] = ti[k];
        }
    }
}

// ============================================================================
// Kernel 3: tiny PEER expert network per token (4 heads x SwiGLU 16->44->16)
// One block per token, 128 threads (one warp per head).
// ============================================================================
__global__ void moe_small_kernel(const float* __restrict__ x,
                                 const float* __restrict__ wdown,
                                 const float* __restrict__ wup,
                                 const float* __restrict__ aw1,
                                 const float* __restrict__ aw2,
                                 const float* __restrict__ aw3)
{
    __shared__ float s_aw1[HID_A * KNN];
    __shared__ float s_aw3[HID_A * KNN];
    __shared__ float s_aw2[KNN * HID_A];
    __shared__ float s_z[H_HEADS][KNN];
    __shared__ float s_hid[H_HEADS][HID_A];
    __shared__ float s_red[H_HEADS];
    __shared__ float s_wred[4];
    __shared__ float s_xsum;

    const int t = blockIdx.x;
    const int tid = threadIdx.x;
    const int w = tid >> 5;       // head
    const int lane = tid & 31;

    for (int i = tid; i < HID_A * KNN; i += 128) { s_aw1[i] = aw1[i]; s_aw3[i] = aw3[i]; s_aw2[i] = aw2[i]; }

    // xsum = sum_d x[t,d]
    float ps = 0.f;
    for (int i = tid; i < D_DIM; i += 128) ps += x[(size_t)t * D_DIM + i];
#pragma unroll
    for (int off = 16; off > 0; off >>= 1) ps += __shfl_down_sync(0xffffffffu, ps, off);
    if (lane == 0) s_wred[w] = ps;
    __syncthreads();
    if (tid == 0) s_xsum = s_wred[0] + s_wred[1] + s_wred[2] + s_wred[3];
    __syncthreads();
    const float xsum = s_xsum;

    const size_t gbase = ((size_t)t * H_HEADS + w) * KNN;
    if (lane < KNN)
        s_z[w][lane] = xsum * wdown[g_topidx[gbase + lane]];
    __syncwarp();

    for (int a = lane; a < HID_A; a += 32) {
        float d1 = 0.f, d3 = 0.f;
#pragma unroll
        for (int k = 0; k < KNN; ++k) {
            float zz = s_z[w][k];
            d1 = fmaf(zz, s_aw1[a * KNN + k], d1);
            d3 = fmaf(zz, s_aw3[a * KNN + k], d3);
        }
        float sl = d1 / (1.f + __expf(-d1));
        s_hid[w][a] = sl * d3;
    }
    __syncwarp();

    float part = 0.f;
    if (lane < KNN) {
        float o = 0.f;
#pragma unroll
        for (int a = 0; a < HID_A; ++a) o = fmaf(s_hid[w][a], s_aw2[lane * HID_A + a], o);
        int id = g_topidx[gbase + lane];
        part = o * g_gates[gbase + lane] * wup[id];
    }
#pragma unroll
    for (int off = 16; off > 0; off >>= 1) part += __shfl_down_sync(0xffffffffu, part, off);
    if (lane == 0) s_red[w] = part;
    __syncthreads();
    if (tid == 0) g_comb[t] = s_red[0] + s_red[1] + s_red[2] + s_red[3];
}

// ============================================================================
// Kernel 4: hid = silu(x @ s_w1^T) * (x @ s_w3^T)   M=2048, N=1024, K=768
// ============================================================================
__global__ void swiglu_hid_kernel(const float* __restrict__ x,
                                  const float* __restrict__ w1,
                                  const float* __restrict__ w3)
{
    __shared__ float sA[16][65];
    __shared__ float sB1[16][65];
    __shared__ float sB3[16][65];
    const int m0 = blockIdx.x * 64;
    const int n0 = blockIdx.y * 64;
    const int tid = threadIdx.x;
    const int kk = tid & 15, r = tid >> 4;
    const int ty = tid >> 4, tx = tid & 15;

    float acc1[4][4] = {};
    float acc3[4][4] = {};
    for (int k0 = 0; k0 < D_DIM; k0 += 16) {
#pragma unroll
        for (int s = 0; s < 4; ++s) {
            sA[kk][r + 16 * s]  = x[(size_t)(m0 + r + 16 * s) * D_DIM + k0 + kk];
            sB1[kk][r + 16 * s] = w1[(size_t)(n0 + r + 16 * s) * D_DIM + k0 + kk];
            sB3[kk][r + 16 * s] = w3[(size_t)(n0 + r + 16 * s) * D_DIM + k0 + kk];
        }
        __syncthreads();
#pragma unroll
        for (int k = 0; k < 16; ++k) {
            float a[4], b1[4], b3[4];
#pragma unroll
            for (int i = 0; i < 4; ++i) {
                a[i]  = sA[k][ty + 16 * i];
                b1[i] = sB1[k][tx + 16 * i];
                b3[i] = sB3[k][tx + 16 * i];
            }
#pragma unroll
            for (int i = 0; i < 4; ++i)
#pragma unroll
                for (int j = 0; j < 4; ++j) {
                    acc1[i][j] = fmaf(a[i], b1[j], acc1[i][j]);
                    acc3[i][j] = fmaf(a[i], b3[j], acc3[i][j]);
                }
        }
        __syncthreads();
    }
#pragma unroll
    for (int i = 0; i < 4; ++i)
#pragma unroll
        for (int j = 0; j < 4; ++j) {
            int m = m0 + ty + 16 * i;
            int n = n0 + tx + 16 * j;
            float v1 = acc1[i][j];
            float sl = v1 / (1.f + __expf(-v1));
            g_hid[(size_t)m * HID_S + n] = sl * acc3[i][j];
        }
}

// ============================================================================
// Kernel 5: out = hid @ s_w2^T + comb[t]     M=2048, N=768, K=1024
// ============================================================================
__global__ void out_kernel(const float* __restrict__ w2, float* __restrict__ out)
{
    __shared__ float sA[16][65];
    __shared__ float sB[16][65];
    const int m0 = blockIdx.x * 64;
    const int n0 = blockIdx.y * 64;
    const int tid = threadIdx.x;
    const int kk = tid & 15, r = tid >> 4;
    const int ty = tid >> 4, tx = tid & 15;

    float acc[4][4] = {};
    for (int k0 = 0; k0 < HID_S; k0 += 16) {
#pragma unroll
        for (int s = 0; s < 4; ++s) {
            sA[kk][r + 16 * s] = g_hid[(size_t)(m0 + r + 16 * s) * HID_S + k0 + kk];
            sB[kk][r + 16 * s] = w2[(size_t)(n0 + r + 16 * s) * HID_S + k0 + kk];
        }
        __syncthreads();
#pragma unroll
        for (int k = 0; k < 16; ++k) {
            float a[4], b[4];
#pragma unroll
            for (int i = 0; i < 4; ++i) { a[i] = sA[k][ty + 16 * i]; b[i] = sB[k][tx + 16 * i]; }
#pragma unroll
            for (int i = 0; i < 4; ++i)
#pragma unroll
                for (int j = 0; j < 4; ++j) acc[i][j] = fmaf(a[i], b[j], acc[i][j]);
        }
        __syncthreads();
    }
#pragma unroll
    for (int i = 0; i < 4; ++i) {
        int m = m0 + ty + 16 * i;
        float c = g_comb[m];
#pragma unroll
        for (int j = 0; j < 4; ++j) {
            int n = n0 + tx + 16 * j;
            out[(size_t)m * D_DIM + n] = acc[i][j] + c;
        }
    }
}

// ============================================================================
extern "C" void kernel_launch(void* const* d_in, const int* in_sizes, int n_in,
                              void* d_out, int out_size)
{
    const float* x        = (const float*)d_in[0];
    const float* wq       = (const float*)d_in[1];
    const float* bq       = (const float*)d_in[2];
    const float* bn_gamma = (const float*)d_in[3];
    const float* bn_beta  = (const float*)d_in[4];
    const float* bn_mean  = (const float*)d_in[5];
    const float* bn_var   = (const float*)d_in[6];
    const float* keys     = (const float*)d_in[7];
    const float* w_down   = (const float*)d_in[8];
    const float* w_up     = (const float*)d_in[9];
    const float* a_w1     = (const float*)d_in[10];
    const float* a_w2     = (const float*)d_in[11];
    const float* a_w3     = (const float*)d_in[12];
    const float* s_w1     = (const float*)d_in[13];
    const float* s_w2     = (const float*)d_in[14];
    const float* s_w3     = (const float*)d_in[15];
    float* out            = (float*)d_out;

    const int scores_smem = (128 * SKS + 32 * SKS + 32 * SKS + 32 * KNN) * 4 + 32 * KNN * 4;
    cudaFuncSetAttribute(scores_topk_kernel,
                         cudaFuncAttributeMaxDynamicSharedMemorySize, scores_smem);

    qproj_kernel<<<dim3(T_TOK / 64, QDIM / 64), 256>>>(x, wq, bq, bn_gamma, bn_beta, bn_mean, bn_var);
    scores_topk_kernel<<<dim3(T_TOK / 32, H_HEADS), 128, scores_smem>>>(keys);
    moe_small_kernel<<<T_TOK, 128>>>(x, w_down, w_up, a_w1, a_w2, a_w3);
    swiglu_hid_kernel<<<dim3(T_TOK / 64, HID_S / 64), 256>>>(x, s_w1, s_w3);
    out_kernel<<<dim3(T_TOK / 64, D_DIM / 64), 256>>>(s_w2, out);
}

// round 4
// speedup vs baseline: 1.7028x; 1.7028x over previous
#include <cuda_runtime.h>
#include <cuda_bf16.h>
#include <cfloat>
#include <math.h>
#include <cstdint>

#define T_TOK   2048
#define D_DIM   768
#define H_HEADS 4
#define N_KEYS  25600
#define KD      128
#define KNN     16
#define HID_A   44
#define HID_S   1024
#define QDIM    (H_HEADS*KD)   // 512
#define BN_EPS  1e-5f

#define KEY_SPLITS 2
#define KEYS_PER_SPLIT (N_KEYS / KEY_SPLITS)   // 12800
#define CHUNK_N 128
#define NCHUNK (KEYS_PER_SPLIT / CHUNK_N)      // 100
#define TOK_TILE 128

// ---------------- scratch (device globals; no allocations allowed) ----------
__device__ __nv_bfloat16 g_qhi[T_TOK * QDIM];
__device__ __nv_bfloat16 g_qlo[T_TOK * QDIM];
__device__ __nv_bfloat16 g_khi[H_HEADS * N_KEYS * KD];
__device__ __nv_bfloat16 g_klo[H_HEADS * N_KEYS * KD];
__device__ float g_ptopv[T_TOK * H_HEADS * KEY_SPLITS * KNN];
__device__ int   g_ptopi[T_TOK * H_HEADS * KEY_SPLITS * KNN];
__device__ int   g_topidx[T_TOK * H_HEADS * KNN];
__device__ float g_gates[T_TOK * H_HEADS * KNN];
__device__ float g_comb[T_TOK];
__device__ float g_hid[T_TOK * HID_S];

// ============================================================================
// helpers
// ============================================================================
__device__ __forceinline__ uint32_t smem_u32(const void* p) {
    uint32_t a;
    asm("{ .reg .u64 t; cvta.to.shared.u64 t, %1; cvt.u32.u64 %0, t; }" : "=r"(a) : "l"(p));
    return a;
}
#define CP_ASYNC16(dst, src) \
    asm volatile("cp.async.cg.shared.global [%0], [%1], 16;" :: "r"((uint32_t)(dst)), "l"(src))
#define CP_COMMIT() asm volatile("cp.async.commit_group;" ::: "memory")
#define CP_WAIT0()  asm volatile("cp.async.wait_group 0;" ::: "memory")

__device__ __forceinline__ void ldmx4(uint32_t& r0, uint32_t& r1, uint32_t& r2, uint32_t& r3,
                                      uint32_t addr) {
    asm volatile("ldmatrix.sync.aligned.m8n8.x4.shared.b16 {%0,%1,%2,%3}, [%4];"
                 : "=r"(r0), "=r"(r1), "=r"(r2), "=r"(r3) : "r"(addr));
}
__device__ __forceinline__ void mma_bf16(float* c, const uint32_t* a, const uint32_t* b) {
    asm volatile(
        "mma.sync.aligned.m16n8k16.row.col.f32.bf16.bf16.f32 "
        "{%0,%1,%2,%3}, {%4,%5,%6,%7}, {%8,%9}, {%0,%1,%2,%3};"
        : "+f"(c[0]), "+f"(c[1]), "+f"(c[2]), "+f"(c[3])
        : "r"(a[0]), "r"(a[1]), "r"(a[2]), "r"(a[3]), "r"(b[0]), "r"(b[1]));
}

// ============================================================================
// keysprep: fp32 keys -> bf16 hi/lo split
// ============================================================================
__global__ void keysprep_kernel(const float* __restrict__ keys)
{
    size_t i = (size_t)blockIdx.x * 256 + threadIdx.x;      // each handles 4 elems
    const float4 v = ((const float4*)keys)[i];
    float f[4] = {v.x, v.y, v.z, v.w};
    __nv_bfloat16 h[4], l[4];
#pragma unroll
    for (int k = 0; k < 4; ++k) {
        h[k] = __float2bfloat16(f[k]);
        l[k] = __float2bfloat16(f[k] - __bfloat162float(h[k]));
    }
    ((__nv_bfloat162*)g_khi)[2 * i]     = __nv_bfloat162(h[0], h[1]);
    ((__nv_bfloat162*)g_khi)[2 * i + 1] = __nv_bfloat162(h[2], h[3]);
    ((__nv_bfloat162*)g_klo)[2 * i]     = __nv_bfloat162(l[0], l[1]);
    ((__nv_bfloat162*)g_klo)[2 * i + 1] = __nv_bfloat162(l[2], l[3]);
}

// ============================================================================
// Kernel 1: q = BN(x @ wq^T + bq), epilogue writes bf16 hi/lo split
// ============================================================================
__global__ void qproj_kernel(const float* __restrict__ x,
                             const float* __restrict__ wq,
                             const float* __restrict__ bq,
                             const float* __restrict__ gamma,
                             const float* __restrict__ beta,
                             const float* __restrict__ mean,
                             const float* __restrict__ var)
{
    __shared__ float sA[16][65];
    __shared__ float sB[16][65];
    const int m0 = blockIdx.x * 64;
    const int n0 = blockIdx.y * 64;
    const int tid = threadIdx.x;
    const int kk = tid & 15, r = tid >> 4;
    const int ty = tid >> 4, tx = tid & 15;

    float acc[4][4] = {};
    for (int k0 = 0; k0 < D_DIM; k0 += 16) {
#pragma unroll
        for (int s = 0; s < 4; ++s) {
            sA[kk][r + 16 * s] = x[(size_t)(m0 + r + 16 * s) * D_DIM + k0 + kk];
            sB[kk][r + 16 * s] = wq[(size_t)(n0 + r + 16 * s) * D_DIM + k0 + kk];
        }
        __syncthreads();
#pragma unroll
        for (int k = 0; k < 16; ++k) {
            float a[4], b[4];
#pragma unroll
            for (int i = 0; i < 4; ++i) { a[i] = sA[k][ty + 16 * i]; b[i] = sB[k][tx + 16 * i]; }
#pragma unroll
            for (int i = 0; i < 4; ++i)
#pragma unroll
                for (int j = 0; j < 4; ++j) acc[i][j] = fmaf(a[i], b[j], acc[i][j]);
        }
        __syncthreads();
    }
#pragma unroll
    for (int i = 0; i < 4; ++i)
#pragma unroll
        for (int j = 0; j < 4; ++j) {
            int m = m0 + ty + 16 * i;
            int n = n0 + tx + 16 * j;
            float v = acc[i][j] + bq[n];
            v = (v - mean[n]) * rsqrtf(var[n] + BN_EPS) * gamma[n] + beta[n];
            __nv_bfloat16 hv = __float2bfloat16(v);
            g_qhi[(size_t)m * QDIM + n] = hv;
            g_qlo[(size_t)m * QDIM + n] = __float2bfloat16(v - __bfloat162float(hv));
        }
}

// ============================================================================
// Kernel 2: scores via mma.sync bf16 (3-term hi/lo split) + fused top-16.
// 256 threads (8 warps, 2x4), tile 128 tokens x 128-key chunks, 100 chunks.
// ============================================================================
#define AB_STRIDE 272          // bytes per row in smem A/B tiles (256 data + 16 pad)
#define SMS_A_HI  0            // 128*272 = 34816
#define SMS_A_LO  34816
#define SMS_B_HI  69632
#define SMS_B_LO  104448
#define SMS_S     139264       // float[128][132] = 67584
#define SMS_TOPV  206848       // float[128*17]
#define SMS_TOPI  215552       // int[128*17]
#define SMS_TOTAL 224256
#define S_STRIDE  132

__global__ void __launch_bounds__(256, 1) scores_mma_kernel()
{
    extern __shared__ char smem[];
    const uint32_t smb = smem_u32(smem);
    const int tid  = threadIdx.x;
    const int wid  = tid >> 5;
    const int lane = tid & 31;

    const int t0 = blockIdx.x * TOK_TILE;
    const int h  = blockIdx.y;
    const int z  = blockIdx.z;
    const int keybase = z * KEYS_PER_SPLIT;

    const int warp_m = wid >> 2;          // 0..1  -> tokens 64*warp_m
    const int warp_n = wid & 3;           // 0..3  -> keys   32*warp_n

    // ---- stage A (q tile hi/lo) + first B chunk via cp.async ----
    {
        const char* qh = (const char*)(g_qhi + (size_t)t0 * QDIM + h * KD);
        const char* ql = (const char*)(g_qlo + (size_t)t0 * QDIM + h * KD);
#pragma unroll
        for (int i = 0; i < 8; ++i) {
            int idx = tid + i * 256;
            int r = idx >> 4, seg = idx & 15;
            uint32_t doff = (uint32_t)(r * AB_STRIDE + seg * 16);
            CP_ASYNC16(smb + SMS_A_HI + doff, qh + (size_t)r * (QDIM * 2) + seg * 16);
            CP_ASYNC16(smb + SMS_A_LO + doff, ql + (size_t)r * (QDIM * 2) + seg * 16);
        }
    }
    const char* khbase = (const char*)(g_khi + ((size_t)h * N_KEYS + keybase) * KD);
    const char* klbase = (const char*)(g_klo + ((size_t)h * N_KEYS + keybase) * KD);
    {
#pragma unroll
        for (int i = 0; i < 8; ++i) {
            int idx = tid + i * 256;
            int r = idx >> 4, seg = idx & 15;
            uint32_t doff = (uint32_t)(r * AB_STRIDE + seg * 16);
            uint32_t soff = (uint32_t)(r * 256 + seg * 16);
            CP_ASYNC16(smb + SMS_B_HI + doff, khbase + soff);
            CP_ASYNC16(smb + SMS_B_LO + doff, klbase + soff);
        }
        CP_COMMIT();
    }

    // topk state (smem, per token)
    float* tvAll = (float*)(smem + SMS_TOPV);
    int*   tiAll = (int*)(smem + SMS_TOPI);
    if (tid < TOK_TILE) {
#pragma unroll
        for (int k = 0; k < KNN; ++k) tvAll[tid * 17 + k] = -FLT_MAX;
    }
    float minv = -FLT_MAX;

    // per-thread invariant ldmatrix address pieces
    // A: row = warp_m*64 + itile*16 + (lane&15); col16 = lane>>4
    const uint32_t a_row_off = (uint32_t)((warp_m * 64 + (lane & 15)) * AB_STRIDE + (lane >> 4) * 16);
    // B: row = warp_n*32 + jpair*16 + (lane&7) + ((lane>>4)<<3); col16 = (lane>>3)&1
    const uint32_t b_row_off = (uint32_t)((warp_n * 32 + (lane & 7) + ((lane >> 4) << 3)) * AB_STRIDE
                                          + ((lane >> 3) & 1) * 16);

    float* sS = (float*)(smem + SMS_S);

    for (int c = 0; c < NCHUNK; ++c) {
        CP_WAIT0();
        __syncthreads();              // B(c) staged everywhere; sS scan of c-1 done

        float C[4][4][4];
#pragma unroll
        for (int i = 0; i < 4; ++i)
#pragma unroll
            for (int j = 0; j < 4; ++j)
#pragma unroll
                for (int e = 0; e < 4; ++e) C[i][j][e] = 0.f;

#pragma unroll
        for (int ks = 0; ks < 8; ++ks) {
            const uint32_t koff = (uint32_t)(ks * 32);
            uint32_t bh[8], bl[8];
            ldmx4(bh[0], bh[1], bh[2], bh[3], smb + SMS_B_HI + b_row_off + koff);
            ldmx4(bh[4], bh[5], bh[6], bh[7], smb + SMS_B_HI + b_row_off + koff + 16 * AB_STRIDE);
            ldmx4(bl[0], bl[1], bl[2], bl[3], smb + SMS_B_LO + b_row_off + koff);
            ldmx4(bl[4], bl[5], bl[6], bl[7], smb + SMS_B_LO + b_row_off + koff + 16 * AB_STRIDE);
#pragma unroll
            for (int i = 0; i < 4; ++i) {
                uint32_t ah[4], al[4];
                ldmx4(ah[0], ah[1], ah[2], ah[3],
                      smb + SMS_A_HI + a_row_off + koff + (uint32_t)(i * 16 * AB_STRIDE));
#pragma unroll
                for (int j = 0; j < 4; ++j) mma_bf16(C[i][j], ah, bh + 2 * j);   // hi*hi
#pragma unroll
                for (int j = 0; j < 4; ++j) mma_bf16(C[i][j], ah, bl + 2 * j);   // hi*lo
                ldmx4(al[0], al[1], al[2], al[3],
                      smb + SMS_A_LO + a_row_off + koff + (uint32_t)(i * 16 * AB_STRIDE));
#pragma unroll
                for (int j = 0; j < 4; ++j) mma_bf16(C[i][j], al, bh + 2 * j);   // lo*hi
            }
        }
        __syncthreads();              // all warps done reading sB

        // prefetch next B chunk (overlaps epilogue)
        if (c + 1 < NCHUNK) {
            const uint32_t cb = (uint32_t)((c + 1) * CHUNK_N * KD * 2);
#pragma unroll
            for (int i = 0; i < 8; ++i) {
                int idx = tid + i * 256;
                int r = idx >> 4, seg = idx & 15;
                uint32_t doff = (uint32_t)(r * AB_STRIDE + seg * 16);
                uint32_t soff = cb + (uint32_t)(r * 256 + seg * 16);
                CP_ASYNC16(smb + SMS_B_HI + doff, khbase + soff);
                CP_ASYNC16(smb + SMS_B_LO + doff, klbase + soff);
            }
            CP_COMMIT();
        }

        // write scores to sS
        const int trow = lane >> 2;
        const int tcol = (lane & 3) * 2;
#pragma unroll
        for (int i = 0; i < 4; ++i) {
            int tok = warp_m * 64 + i * 16 + trow;
#pragma unroll
            for (int j = 0; j < 4; ++j) {
                int key = warp_n * 32 + j * 8 + tcol;
                *(float2*)(sS + (size_t)tok * S_STRIDE + key)       = make_float2(C[i][j][0], C[i][j][1]);
                *(float2*)(sS + (size_t)(tok + 8) * S_STRIDE + key) = make_float2(C[i][j][2], C[i][j][3]);
            }
        }
        __syncthreads();

        // top-16 scan: one thread per token
        if (tid < TOK_TILE) {
            float* tv = tvAll + tid * 17;
            int*   ti = tiAll + tid * 17;
            const float4* row = (const float4*)(sS + (size_t)tid * S_STRIDE);
            const int n0 = keybase + c * CHUNK_N;
#pragma unroll 4
            for (int j4 = 0; j4 < 32; ++j4) {
                float4 v = row[j4];
                int base = n0 + 4 * j4;
#pragma unroll
                for (int e = 0; e < 4; ++e) {
                    float vv = (e == 0) ? v.x : (e == 1) ? v.y : (e == 2) ? v.z : v.w;
                    if (vv > minv) {
                        int p = KNN - 1;
                        while (p > 0 && tv[p - 1] < vv) { tv[p] = tv[p - 1]; ti[p] = ti[p - 1]; --p; }
                        tv[p] = vv; ti[p] = base + e;
                        minv = tv[KNN - 1];
                    }
                }
            }
        }
        // next loop-top CP_WAIT0+sync orders sS rewrite after scan
    }

    // write partial top-16 lists
    if (tid < TOK_TILE) {
        int t = t0 + tid;
        size_t pb = (((size_t)t * H_HEADS + h) * KEY_SPLITS + z) * KNN;
        float* tv = tvAll + tid * 17;
        int*   ti = tiAll + tid * 17;
#pragma unroll
        for (int k = 0; k < KNN; ++k) { g_ptopv[pb + k] = tv[k]; g_ptopi[pb + k] = ti[k]; }
    }
}

// ============================================================================
// Kernel 2b: merge the two key-split top-16 lists, softmax -> gates
// ============================================================================
__global__ void merge_gates_kernel()
{
    int i = blockIdx.x * blockDim.x + threadIdx.x;   // (t*H + h)
    if (i >= T_TOK * H_HEADS) return;
    const float* av = g_ptopv + (size_t)i * KEY_SPLITS * KNN;
    const int*   ai = g_ptopi + (size_t)i * KEY_SPLITS * KNN;
    const float* bv = av + KNN;
    const int*   bi = ai + KNN;

    float v[KNN]; int ix[KNN];
    int pa = 0, pb = 0;
#pragma unroll
    for (int k = 0; k < KNN; ++k) {
        float va = av[pa], vb = bv[pb];
        if (va >= vb) { v[k] = va; ix[k] = ai[pa]; ++pa; }
        else          { v[k] = vb; ix[k] = bi[pb]; ++pb; }
    }
    float mx = v[0], sum = 0.f, e[KNN];
#pragma unroll
    for (int k = 0; k < KNN; ++k) { e[k] = __expf(v[k] - mx); sum += e[k]; }
    float inv = 1.f / sum;
    size_t base = (size_t)i * KNN;
#pragma unroll
    for (int k = 0; k < KNN; ++k) { g_gates[base + k] = e[k] * inv; g_topidx[base + k] = ix[k]; }
}

// ============================================================================
// Kernel 3: tiny PEER expert network per token (4 heads x SwiGLU 16->44->16)
// ============================================================================
__global__ void moe_small_kernel(const float* __restrict__ x,
                                 const float* __restrict__ wdown,
                                 const float* __restrict__ wup,
                                 const float* __restrict__ aw1,
                                 const float* __restrict__ aw2,
                                 const float* __restrict__ aw3)
{
    __shared__ float s_aw1[HID_A * KNN];
    __shared__ float s_aw3[HID_A * KNN];
    __shared__ float s_aw2[KNN * HID_A];
    __shared__ float s_z[H_HEADS][KNN];
    __shared__ float s_hid[H_HEADS][HID_A];
    __shared__ float s_red[H_HEADS];
    __shared__ float s_wred[4];
    __shared__ float s_xsum;

    const int t = blockIdx.x;
    const int tid = threadIdx.x;
    const int w = tid >> 5;
    const int lane = tid & 31;

    for (int i = tid; i < HID_A * KNN; i += 128) { s_aw1[i] = aw1[i]; s_aw3[i] = aw3[i]; s_aw2[i] = aw2[i]; }

    float ps = 0.f;
    for (int i = tid; i < D_DIM; i += 128) ps += x[(size_t)t * D_DIM + i];
#pragma unroll
    for (int off = 16; off > 0; off >>= 1) ps += __shfl_down_sync(0xffffffffu, ps, off);
    if (lane == 0) s_wred[w] = ps;
    __syncthreads();
    if (tid == 0) s_xsum = s_wred[0] + s_wred[1] + s_wred[2] + s_wred[3];
    __syncthreads();
    const float xsum = s_xsum;

    const size_t gbase = ((size_t)t * H_HEADS + w) * KNN;
    if (lane < KNN)
        s_z[w][lane] = xsum * wdown[g_topidx[gbase + lane]];
    __syncwarp();

    for (int a = lane; a < HID_A; a += 32) {
        float d1 = 0.f, d3 = 0.f;
#pragma unroll
        for (int k = 0; k < KNN; ++k) {
            float zz = s_z[w][k];
            d1 = fmaf(zz, s_aw1[a * KNN + k], d1);
            d3 = fmaf(zz, s_aw3[a * KNN + k], d3);
        }
        float sl = d1 / (1.f + __expf(-d1));
        s_hid[w][a] = sl * d3;
    }
    __syncwarp();

    float part = 0.f;
    if (lane < KNN) {
        float o = 0.f;
#pragma unroll
        for (int a = 0; a < HID_A; ++a) o = fmaf(s_hid[w][a], s_aw2[lane * HID_A + a], o);
        int id = g_topidx[gbase + lane];
        part = o * g_gates[gbase + lane] * wup[id];
    }
#pragma unroll
    for (int off = 16; off > 0; off >>= 1) part += __shfl_down_sync(0xffffffffu, part, off);
    if (lane == 0) s_red[w] = part;
    __syncthreads();
    if (tid == 0) g_comb[t] = s_red[0] + s_red[1] + s_red[2] + s_red[3];
}

// ============================================================================
// Kernel 4: hid = silu(x @ s_w1^T) * (x @ s_w3^T)
// ============================================================================
__global__ void swiglu_hid_kernel(const float* __restrict__ x,
                                  const float* __restrict__ w1,
                                  const float* __restrict__ w3)
{
    __shared__ float sA[16][65];
    __shared__ float sB1[16][65];
    __shared__ float sB3[16][65];
    const int m0 = blockIdx.x * 64;
    const int n0 = blockIdx.y * 64;
    const int tid = threadIdx.x;
    const int kk = tid & 15, r = tid >> 4;
    const int ty = tid >> 4, tx = tid & 15;

    float acc1[4][4] = {};
    float acc3[4][4] = {};
    for (int k0 = 0; k0 < D_DIM; k0 += 16) {
#pragma unroll
        for (int s = 0; s < 4; ++s) {
            sA[kk][r + 16 * s]  = x[(size_t)(m0 + r + 16 * s) * D_DIM + k0 + kk];
            sB1[kk][r + 16 * s] = w1[(size_t)(n0 + r + 16 * s) * D_DIM + k0 + kk];
            sB3[kk][r + 16 * s] = w3[(size_t)(n0 + r + 16 * s) * D_DIM + k0 + kk];
        }
        __syncthreads();
#pragma unroll
        for (int k = 0; k < 16; ++k) {
            float a[4], b1[4], b3[4];
#pragma unroll
            for (int i = 0; i < 4; ++i) {
                a[i]  = sA[k][ty + 16 * i];
                b1[i] = sB1[k][tx + 16 * i];
                b3[i] = sB3[k][tx + 16 * i];
            }
#pragma unroll
            for (int i = 0; i < 4; ++i)
#pragma unroll
                for (int j = 0; j < 4; ++j) {
                    acc1[i][j] = fmaf(a[i], b1[j], acc1[i][j]);
                    acc3[i][j] = fmaf(a[i], b3[j], acc3[i][j]);
                }
        }
        __syncthreads();
    }
#pragma unroll
    for (int i = 0; i < 4; ++i)
#pragma unroll
        for (int j = 0; j < 4; ++j) {
            int m = m0 + ty + 16 * i;
            int n = n0 + tx + 16 * j;
            float v1 = acc1[i][j];
            float sl = v1 / (1.f + __expf(-v1));
            g_hid[(size_t)m * HID_S + n] = sl * acc3[i][j];
        }
}

// ============================================================================
// Kernel 5: out = hid @ s_w2^T + comb[t]
// ============================================================================
__global__ void out_kernel(const float* __restrict__ w2, float* __restrict__ out)
{
    __shared__ float sA[16][65];
    __shared__ float sB[16][65];
    const int m0 = blockIdx.x * 64;
    const int n0 = blockIdx.y * 64;
    const int tid = threadIdx.x;
    const int kk = tid & 15, r = tid >> 4;
    const int ty = tid >> 4, tx = tid & 15;

    float acc[4][4] = {};
    for (int k0 = 0; k0 < HID_S; k0 += 16) {
#pragma unroll
        for (int s = 0; s < 4; ++s) {
            sA[kk][r + 16 * s] = g_hid[(size_t)(m0 + r + 16 * s) * HID_S + k0 + kk];
            sB[kk][r + 16 * s] = w2[(size_t)(n0 + r + 16 * s) * HID_S + k0 + kk];
        }
        __syncthreads();
#pragma unroll
        for (int k = 0; k < 16; ++k) {
            float a[4], b[4];
#pragma unroll
            for (int i = 0; i < 4; ++i) { a[i] = sA[k][ty + 16 * i]; b[i] = sB[k][tx + 16 * i]; }
#pragma unroll
            for (int i = 0; i < 4; ++i)
#pragma unroll
                for (int j = 0; j < 4; ++j) acc[i][j] = fmaf(a[i], b[j], acc[i][j]);
        }
        __syncthreads();
    }
#pragma unroll
    for (int i = 0; i < 4; ++i) {
        int m = m0 + ty + 16 * i;
        float c = g_comb[m];
#pragma unroll
        for (int j = 0; j < 4; ++j) {
            int n = n0 + tx + 16 * j;
            out[(size_t)m * D_DIM + n] = acc[i][j] + c;
        }
    }
}

// ============================================================================
extern "C" void kernel_launch(void* const* d_in, const int* in_sizes, int n_in,
                              void* d_out, int out_size)
{
    const float* x        = (const float*)d_in[0];
    const float* wq       = (const float*)d_in[1];
    const float* bq       = (const float*)d_in[2];
    const float* bn_gamma = (const float*)d_in[3];
    const float* bn_beta  = (const float*)d_in[4];
    const float* bn_mean  = (const float*)d_in[5];
    const float* bn_var   = (const float*)d_in[6];
    const float* keys     = (const float*)d_in[7];
    const float* w_down   = (const float*)d_in[8];
    const float* w_up     = (const float*)d_in[9];
    const float* a_w1     = (const float*)d_in[10];
    const float* a_w2     = (const float*)d_in[11];
    const float* a_w3     = (const float*)d_in[12];
    const float* s_w1     = (const float*)d_in[13];
    const float* s_w2     = (const float*)d_in[14];
    const float* s_w3     = (const float*)d_in[15];
    float* out            = (float*)d_out;

    cudaFuncSetAttribute(scores_mma_kernel,
                         cudaFuncAttributeMaxDynamicSharedMemorySize, SMS_TOTAL);

    keysprep_kernel<<<(H_HEADS * N_KEYS * KD) / (256 * 4), 256>>>(keys);
    qproj_kernel<<<dim3(T_TOK / 64, QDIM / 64), 256>>>(x, wq, bq, bn_gamma, bn_beta, bn_mean, bn_var);
    scores_mma_kernel<<<dim3(T_TOK / TOK_TILE, H_HEADS, KEY_SPLITS), 256, SMS_TOTAL>>>();
    merge_gates_kernel<<<(T_TOK * H_HEADS + 255) / 256, 256>>>();
    moe_small_kernel<<<T_TOK, 128>>>(x, w_down, w_up, a_w1, a_w2, a_w3);
    swiglu_hid_kernel<<<dim3(T_TOK / 64, HID_S / 64), 256>>>(x, s_w1, s_w3);
    out_kernel<<<dim3(T_TOK / 64, D_DIM / 64), 256>>>(s_w2, out);
}